// round 12
// baseline (speedup 1.0000x reference)
#include <cuda_runtime.h>

// ---------------- problem constants ----------------
#define NLAYER 4
#define BSZ    4
#define SEQ    2048
#define PLEN   1024
#define DMODEL 512
#define DFF    2048
#define NH     8
#define DHEAD  64
#define MROWS  (BSZ * SEQ)      // 8192 token rows

// ---------------- scratch (device globals: no allocation allowed) ----------
__device__ float g_x   [(size_t)MROWS * DMODEL];       // 16 MB residual stream
__device__ float g_qkv [(size_t)MROWS * 3 * DMODEL];   // 48 MB qkv / reused as tmp
__device__ float g_attn[(size_t)MROWS * DMODEL];       // 16 MB attn out / ffn2 out
__device__ float g_hid [(size_t)MROWS * DFF];          // 64 MB ffn hidden / proj tmp

// ============================================================================
// Generic SGEMM: C[M,N] = A[M,K] @ B[K,N] + bias[N], optional ReLU.
// 128x128 block tile, BK=16, 256 threads, 8x8 microtile, double-buffered smem.
// All of M,N,K are multiples of the tile sizes for this problem.
// ============================================================================
__global__ __launch_bounds__(256, 2)
void sgemm_bias_act(const float* __restrict__ A, const float* __restrict__ Bm,
                    const float* __restrict__ bias, float* __restrict__ C,
                    int M, int N, int K, int relu)
{
    constexpr int BM = 128, BN = 128, BK = 16, LDA = BM + 4;
    __shared__ float As[2][BK][LDA];   // A stored transposed [k][m], padded
    __shared__ float Bs[2][BK][BN];    // B stored natural    [k][n]

    const int tid = threadIdx.x;
    const int bm  = blockIdx.y * BM;
    const int bn  = blockIdx.x * BN;
    const int ty  = tid >> 4;          // 0..15 (row group)
    const int tx  = tid & 15;          // 0..15 (col group)

    float acc[8][8];
#pragma unroll
    for (int i = 0; i < 8; i++)
#pragma unroll
        for (int j = 0; j < 8; j++) acc[i][j] = 0.f;

    float4 pa[2], pb[2];

    // preload tile k0 = 0
#pragma unroll
    for (int it = 0; it < 2; it++) {
        int idx = tid + it * 256;
        pa[it] = *(const float4*)(A  + (size_t)(bm + (idx >> 2)) * K + ((idx & 3) << 2));
        pb[it] = *(const float4*)(Bm + (size_t)(idx >> 5) * N + bn + ((idx & 31) << 2));
    }
#pragma unroll
    for (int it = 0; it < 2; it++) {
        int idx = tid + it * 256;
        int ar = idx >> 2, ac = (idx & 3) << 2;
        As[0][ac + 0][ar] = pa[it].x;
        As[0][ac + 1][ar] = pa[it].y;
        As[0][ac + 2][ar] = pa[it].z;
        As[0][ac + 3][ar] = pa[it].w;
        *(float4*)&Bs[0][idx >> 5][(idx & 31) << 2] = pb[it];
    }
    __syncthreads();

    int buf = 0;
    for (int k0 = 0; k0 < K; k0 += BK) {
        const int knext = k0 + BK;
        if (knext < K) {
#pragma unroll
            for (int it = 0; it < 2; it++) {
                int idx = tid + it * 256;
                pa[it] = *(const float4*)(A  + (size_t)(bm + (idx >> 2)) * K + knext + ((idx & 3) << 2));
                pb[it] = *(const float4*)(Bm + (size_t)(knext + (idx >> 5)) * N + bn + ((idx & 31) << 2));
            }
        }
#pragma unroll
        for (int kk = 0; kk < BK; kk++) {
            float a[8], b[8];
            *(float4*)(a)     = *(const float4*)&As[buf][kk][ty * 8];
            *(float4*)(a + 4) = *(const float4*)&As[buf][kk][ty * 8 + 4];
            *(float4*)(b)     = *(const float4*)&Bs[buf][kk][tx * 8];
            *(float4*)(b + 4) = *(const float4*)&Bs[buf][kk][tx * 8 + 4];
#pragma unroll
            for (int i = 0; i < 8; i++)
#pragma unroll
                for (int j = 0; j < 8; j++)
                    acc[i][j] = fmaf(a[i], b[j], acc[i][j]);
        }
        if (knext < K) {
            const int nb = buf ^ 1;
#pragma unroll
            for (int it = 0; it < 2; it++) {
                int idx = tid + it * 256;
                int ar = idx >> 2, ac = (idx & 3) << 2;
                As[nb][ac + 0][ar] = pa[it].x;
                As[nb][ac + 1][ar] = pa[it].y;
                As[nb][ac + 2][ar] = pa[it].z;
                As[nb][ac + 3][ar] = pa[it].w;
                *(float4*)&Bs[nb][idx >> 5][(idx & 31) << 2] = pb[it];
            }
            __syncthreads();
            buf = nb;
        }
    }

    // epilogue: bias (+ optional relu), vectorized stores
#pragma unroll
    for (int i = 0; i < 8; i++) {
        const size_t row = (size_t)(bm + ty * 8 + i);
#pragma unroll
        for (int jj = 0; jj < 2; jj++) {
            const int col = bn + tx * 8 + jj * 4;
            float4 bv = *(const float4*)(bias + col);
            float4 o;
            o.x = acc[i][jj * 4 + 0] + bv.x;
            o.y = acc[i][jj * 4 + 1] + bv.y;
            o.z = acc[i][jj * 4 + 2] + bv.z;
            o.w = acc[i][jj * 4 + 3] + bv.w;
            if (relu) {
                o.x = fmaxf(o.x, 0.f); o.y = fmaxf(o.y, 0.f);
                o.z = fmaxf(o.z, 0.f); o.w = fmaxf(o.w, 0.f);
            }
            *(float4*)(C + row * N + col) = o;
        }
    }
}

// ============================================================================
// Fused sparse attention (flash-style).
//   All queries attend to the P=1024 perception keys; gen queries additionally
//   attend to their own (q_l . k_l) diagonal term.
// Grid: (L/64 q-tiles, B*H).  Block: 128 threads (16 row-groups x 8 col-groups),
// per-thread microtile 4 rows x 8 output channels. Online softmax.
// smem: Qs[64][64] (q^T, pre-scaled), KPs[64][68] (K^T then P), Vs[64][64].
// ============================================================================
constexpr int ATTN_SMEM_BYTES = (64 * 64 + 64 * 68 + 64 * 64) * 4;  // 50176

__global__ __launch_bounds__(128)
void attn_kernel(const float* __restrict__ qkv, float* __restrict__ out)
{
    constexpr int L = SEQ, Pp = PLEN, D = DMODEL, DH = DHEAD;
    constexpr int QT = 64, KT = 64, KLD = 68;
    extern __shared__ float sm[];
    float* Qs  = sm;                 // [DH][QT]
    float* KPs = sm + DH * QT;       // [DH][KLD] (K^T), reused as P [KT][KLD]
    float* Vs  = KPs + DH * KLD;     // [KT][DH]

    const int tid = threadIdx.x;
    const int l0  = blockIdx.x * QT;
    const int b   = blockIdx.y >> 3;
    const int h   = blockIdx.y & 7;
    const int rg  = tid >> 3;        // 0..15
    const int cg  = tid & 7;         // 0..7

    const float* qbase = qkv + ((size_t)b * L) * (3 * D) + h * DH;
    const float* kbase = qbase + D;
    const float* vbase = qbase + 2 * D;

    // load Q tile, pre-scaled by 1/sqrt(dh)=0.125, transposed [k][r]
#pragma unroll
    for (int it = 0; it < 8; it++) {
        int idx = tid + it * 128;
        int r = idx >> 4;
        int c = (idx & 15) << 2;
        float4 q4 = *(const float4*)(qbase + (size_t)(l0 + r) * (3 * D) + c);
        Qs[(c + 0) * QT + r] = q4.x * 0.125f;
        Qs[(c + 1) * QT + r] = q4.y * 0.125f;
        Qs[(c + 2) * QT + r] = q4.z * 0.125f;
        Qs[(c + 3) * QT + r] = q4.w * 0.125f;
    }

    float mrow[4], lrow[4], acc[4][8];
#pragma unroll
    for (int i = 0; i < 4; i++) {
        mrow[i] = -1e30f; lrow[i] = 0.f;
#pragma unroll
        for (int j = 0; j < 8; j++) acc[i][j] = 0.f;
    }
    __syncthreads();

    for (int kc = 0; kc < Pp; kc += KT) {
        // load K chunk transposed [k][c] (padded) and V chunk natural [key][c]
#pragma unroll
        for (int it = 0; it < 8; it++) {
            int idx = tid + it * 128;
            int r = idx >> 4;
            int c = (idx & 15) << 2;
            float4 k4 = *(const float4*)(kbase + (size_t)(kc + r) * (3 * D) + c);
            KPs[(c + 0) * KLD + r] = k4.x;
            KPs[(c + 1) * KLD + r] = k4.y;
            KPs[(c + 2) * KLD + r] = k4.z;
            KPs[(c + 3) * KLD + r] = k4.w;
            float4 v4 = *(const float4*)(vbase + (size_t)(kc + r) * (3 * D) + c);
            *(float4*)(Vs + r * DH + c) = v4;
        }
        __syncthreads();

        // S tile: s[4][8] = (scaled Q) . K^T
        float s[4][8];
#pragma unroll
        for (int i = 0; i < 4; i++)
#pragma unroll
            for (int j = 0; j < 8; j++) s[i][j] = 0.f;
#pragma unroll 8
        for (int kk = 0; kk < DH; kk++) {
            float a[4], bv[8];
            *(float4*)a        = *(const float4*)(Qs  + kk * QT  + rg * 4);
            *(float4*)bv       = *(const float4*)(KPs + kk * KLD + cg * 8);
            *(float4*)(bv + 4) = *(const float4*)(KPs + kk * KLD + cg * 8 + 4);
#pragma unroll
            for (int i = 0; i < 4; i++)
#pragma unroll
                for (int j = 0; j < 8; j++)
                    s[i][j] = fmaf(a[i], bv[j], s[i][j]);
        }
        __syncthreads();   // done reading K; KPs will be overwritten with P

        // online softmax per row (8 cg lanes share a row)
#pragma unroll
        for (int i = 0; i < 4; i++) {
            float rmax = s[i][0];
#pragma unroll
            for (int j = 1; j < 8; j++) rmax = fmaxf(rmax, s[i][j]);
            rmax = fmaxf(rmax, __shfl_xor_sync(0xffffffffu, rmax, 1));
            rmax = fmaxf(rmax, __shfl_xor_sync(0xffffffffu, rmax, 2));
            rmax = fmaxf(rmax, __shfl_xor_sync(0xffffffffu, rmax, 4));
            float mnew = fmaxf(mrow[i], rmax);
            float corr = __expf(mrow[i] - mnew);
            mrow[i] = mnew;
            float p[8], rs = 0.f;
#pragma unroll
            for (int j = 0; j < 8; j++) { p[j] = __expf(s[i][j] - mnew); rs += p[j]; }
            rs += __shfl_xor_sync(0xffffffffu, rs, 1);
            rs += __shfl_xor_sync(0xffffffffu, rs, 2);
            rs += __shfl_xor_sync(0xffffffffu, rs, 4);
            lrow[i] = lrow[i] * corr + rs;
#pragma unroll
            for (int j = 0; j < 8; j++) {
                acc[i][j] *= corr;
                KPs[(cg * 8 + j) * KLD + rg * 4 + i] = p[j];   // P as [key][row]
            }
        }
        __syncthreads();

        // O += P @ V
#pragma unroll 8
        for (int kk = 0; kk < KT; kk++) {
            float a[4], bv[8];
            *(float4*)a        = *(const float4*)(KPs + kk * KLD + rg * 4);
            *(float4*)bv       = *(const float4*)(Vs  + kk * DH  + cg * 8);
            *(float4*)(bv + 4) = *(const float4*)(Vs  + kk * DH  + cg * 8 + 4);
#pragma unroll
            for (int i = 0; i < 4; i++)
#pragma unroll
                for (int j = 0; j < 8; j++)
                    acc[i][j] = fmaf(a[i], bv[j], acc[i][j]);
        }
        __syncthreads();
    }

    // diagonal term for gen rows, finalize and write out as [B, L, H*DH]
    const bool isgen = (l0 >= Pp);
#pragma unroll
    for (int i = 0; i < 4; i++) {
        const int r  = rg * 4 + i;
        const int lq = l0 + r;
        if (isgen) {
            const float* ks = kbase + (size_t)lq * (3 * D);
            float part = 0.f;
#pragma unroll
            for (int kk2 = 0; kk2 < 8; kk2++) {
                int k = cg * 8 + kk2;
                part += Qs[k * QT + r] * ks[k];      // Q already carries the scale
            }
            part += __shfl_xor_sync(0xffffffffu, part, 1);
            part += __shfl_xor_sync(0xffffffffu, part, 2);
            part += __shfl_xor_sync(0xffffffffu, part, 4);
            const float dlog = part;
            float mnew = fmaxf(mrow[i], dlog);
            float corr = __expf(mrow[i] - mnew);
            float ed   = __expf(dlog - mnew);
            lrow[i] = lrow[i] * corr + ed;
            const float* vs = vbase + (size_t)lq * (3 * D) + cg * 8;
            float4 v0 = *(const float4*)(vs);
            float4 v1 = *(const float4*)(vs + 4);
            float vv[8] = {v0.x, v0.y, v0.z, v0.w, v1.x, v1.y, v1.z, v1.w};
#pragma unroll
            for (int j = 0; j < 8; j++)
                acc[i][j] = acc[i][j] * corr + ed * vv[j];
        }
        const float inv = 1.f / lrow[i];
        float* op = out + ((size_t)b * L + lq) * D + h * DH + cg * 8;
        float4 o0, o1;
        o0.x = acc[i][0] * inv; o0.y = acc[i][1] * inv;
        o0.z = acc[i][2] * inv; o0.w = acc[i][3] * inv;
        o1.x = acc[i][4] * inv; o1.y = acc[i][5] * inv;
        o1.z = acc[i][6] * inv; o1.w = acc[i][7] * inv;
        *(float4*)op       = o0;
        *(float4*)(op + 4) = o1;
    }
}

// ============================================================================
// Fused residual add + LayerNorm (in-place on x): x = LN(x + delta)*g + b
// One block per row (512 channels), 128 threads x 4 channels.
// ============================================================================
__global__ __launch_bounds__(128)
void add_ln_kernel(float* __restrict__ x, const float* __restrict__ delta,
                   const float* __restrict__ gamma, const float* __restrict__ beta)
{
    __shared__ float rs[4], rq[4];
    const int tid = threadIdx.x;
    const size_t off = (size_t)blockIdx.x * DMODEL + tid * 4;
    float4 a  = *(const float4*)(x + off);
    float4 d4 = *(const float4*)(delta + off);
    float v0 = a.x + d4.x, v1 = a.y + d4.y, v2 = a.z + d4.z, v3 = a.w + d4.w;
    float s = v0 + v1 + v2 + v3;
    float q = v0 * v0 + v1 * v1 + v2 * v2 + v3 * v3;
#pragma unroll
    for (int o = 16; o > 0; o >>= 1) {
        s += __shfl_xor_sync(0xffffffffu, s, o);
        q += __shfl_xor_sync(0xffffffffu, q, o);
    }
    if ((tid & 31) == 0) { rs[tid >> 5] = s; rq[tid >> 5] = q; }
    __syncthreads();
    const float ts = rs[0] + rs[1] + rs[2] + rs[3];
    const float tq = rq[0] + rq[1] + rq[2] + rq[3];
    const float mu   = ts * (1.0f / DMODEL);
    const float var  = tq * (1.0f / DMODEL) - mu * mu;
    const float rstd = rsqrtf(var + 1e-5f);
    float4 g4 = *(const float4*)(gamma + tid * 4);
    float4 b4 = *(const float4*)(beta + tid * 4);
    float4 o;
    o.x = (v0 - mu) * rstd * g4.x + b4.x;
    o.y = (v1 - mu) * rstd * g4.y + b4.y;
    o.z = (v2 - mu) * rstd * g4.z + b4.z;
    o.w = (v3 - mu) * rstd * g4.w + b4.w;
    *(float4*)(x + off) = o;
}

// ============================================================================
// Concat pcpt/gen into x; split x into (pcpt_out, gen_out) at the end.
// ============================================================================
__global__ void concat_in_kernel(const float* __restrict__ pcpt,
                                 const float* __restrict__ gen,
                                 float* __restrict__ x)
{
    const size_t i = (size_t)blockIdx.x * blockDim.x + threadIdx.x;  // float4 id
    const size_t row = i >> 7;            // 128 float4 per row
    const int    c4  = (int)(i & 127);
    const size_t b   = row >> 11;         // / 2048
    const int    l   = (int)(row & 2047);
    const float4* src;
    if (l < PLEN) src = (const float4*)pcpt + ((b * PLEN + l) * 128 + c4);
    else          src = (const float4*)gen  + ((b * PLEN + (l - PLEN)) * 128 + c4);
    ((float4*)x)[i] = *src;
}

__global__ void split_out_kernel(const float* __restrict__ x, float* __restrict__ out)
{
    const size_t i = (size_t)blockIdx.x * blockDim.x + threadIdx.x;  // float4 id
    const size_t row = i >> 7;
    const int    c4  = (int)(i & 127);
    const size_t b   = row >> 11;
    const int    l   = (int)(row & 2047);
    size_t dst;
    if (l < PLEN) dst = (b * PLEN + l) * 128 + c4;
    else          dst = (size_t)BSZ * PLEN * 128 + (b * PLEN + (l - PLEN)) * 128 + c4;
    ((float4*)out)[dst] = ((const float4*)x)[i];
}

// ============================================================================
// kernel_launch: full 4-layer forward. ~30 kernel launches, graph-capturable.
// ============================================================================
extern "C" void kernel_launch(void* const* d_in, const int* in_sizes, int n_in,
                              void* d_out, int out_size)
{
    (void)in_sizes; (void)n_in; (void)out_size;
    const float* pcpt = (const float*)d_in[0];
    const float* gen  = (const float*)d_in[1];
    // d_in[2] = src_key_padding_mask (all false) — unused
    const float* Wqkv = (const float*)d_in[3];
    const float* bqkv = (const float*)d_in[4];
    const float* Wo   = (const float*)d_in[5];
    const float* bo   = (const float*)d_in[6];
    const float* W1   = (const float*)d_in[7];
    const float* b1   = (const float*)d_in[8];
    const float* W2   = (const float*)d_in[9];
    const float* b2   = (const float*)d_in[10];
    const float* g1   = (const float*)d_in[11];
    const float* be1  = (const float*)d_in[12];
    const float* g2   = (const float*)d_in[13];
    const float* be2  = (const float*)d_in[14];
    float* out = (float*)d_out;

    float *x, *qkvb, *attnb, *hid;
    cudaGetSymbolAddress((void**)&x,     g_x);
    cudaGetSymbolAddress((void**)&qkvb,  g_qkv);
    cudaGetSymbolAddress((void**)&attnb, g_attn);
    cudaGetSymbolAddress((void**)&hid,   g_hid);

    // opt-in >48KB dynamic smem for attention (sticky per-function; error
    // during capture — if any — is harmless since the first uncaptured call set it)
    cudaFuncSetAttribute((const void*)attn_kernel,
                         cudaFuncAttributeMaxDynamicSharedMemorySize,
                         ATTN_SMEM_BYTES);

    const int total4 = MROWS * DMODEL / 4;          // 1,048,576 float4
    concat_in_kernel<<<total4 / 256, 256>>>(pcpt, gen, x);

    constexpr int M = MROWS;
    for (int layer = 0; layer < NLAYER; layer++) {
        const float* wq  = Wqkv + (size_t)layer * DMODEL * 3 * DMODEL;
        const float* bq  = bqkv + (size_t)layer * 3 * DMODEL;
        const float* wo  = Wo   + (size_t)layer * DMODEL * DMODEL;
        const float* bob = bo   + (size_t)layer * DMODEL;
        const float* w1  = W1   + (size_t)layer * DMODEL * DFF;
        const float* b1b = b1   + (size_t)layer * DFF;
        const float* w2  = W2   + (size_t)layer * DFF * DMODEL;
        const float* b2b = b2   + (size_t)layer * DMODEL;

        // 1) qkv = x @ Wqkv + bqkv               (8192 x 1536, K=512)
        sgemm_bias_act<<<dim3(3 * DMODEL / 128, M / 128), 256>>>(
            x, wq, bq, qkvb, M, 3 * DMODEL, DMODEL, 0);

        // 2) fused sparse attention -> attnb     [B, L, H*dh]
        attn_kernel<<<dim3(SEQ / 64, BSZ * NH), 128, ATTN_SMEM_BYTES>>>(qkvb, attnb);

        // 3) proj = attn @ Wo + bo -> hid (tmp)  (8192 x 512, K=512)
        sgemm_bias_act<<<dim3(DMODEL / 128, M / 128), 256>>>(
            attnb, wo, bob, hid, M, DMODEL, DMODEL, 0);

        // 4) x = LN(x + proj)
        add_ln_kernel<<<MROWS, 128>>>(x, hid, g1 + layer * DMODEL, be1 + layer * DMODEL);

        // 5) hid = relu(x @ W1 + b1)             (8192 x 2048, K=512)
        sgemm_bias_act<<<dim3(DFF / 128, M / 128), 256>>>(
            x, w1, b1b, hid, M, DFF, DMODEL, 1);

        // 6) attnb = hid @ W2 + b2               (8192 x 512, K=2048)
        sgemm_bias_act<<<dim3(DMODEL / 128, M / 128), 256>>>(
            hid, w2, b2b, attnb, M, DMODEL, DFF, 0);

        // 7) x = LN(x + ffn)
        add_ln_kernel<<<MROWS, 128>>>(x, attnb, g2 + layer * DMODEL, be2 + layer * DMODEL);
    }

    split_out_kernel<<<total4 / 256, 256>>>(x, out);
}

// round 13
// speedup vs baseline: 1.8480x; 1.8480x over previous
#include <cuda_runtime.h>

// ---------------- problem constants ----------------
#define NLAYER 4
#define BSZ    4
#define SEQ    2048
#define PLEN   1024
#define DMODEL 512
#define DFF    2048
#define NH     8
#define DHEAD  64
#define MROWS  (BSZ * SEQ)      // 8192 token rows

// ---------------- scratch (device globals: no allocation allowed) ----------
__device__ float g_x   [(size_t)MROWS * DMODEL];       // 16 MB residual stream
__device__ float g_qkv [(size_t)MROWS * 3 * DMODEL];   // 48 MB qkv
__device__ float g_attn[(size_t)MROWS * DMODEL];       // 16 MB attn out / ffn2 out
__device__ float g_hid [(size_t)MROWS * DFF];          // 64 MB ffn hidden / proj tmp

// ============================================================================
// TF32 tensor-core SGEMM: C[M,N] = A[M,K] @ B[K,N] + bias[N], optional ReLU.
// 128x128x32 tile, 256 threads (8 warps, 2x4), warp tile 64x32 via m16n8k8.
// A smem [128][36] (lda=36 -> conflict-free frag LDS), B smem [32][136].
// Inputs rounded to tf32 with cvt.rna in the producer path.
// ============================================================================
#define GA_LDA 36
#define GB_LDB 136
#define GA_BUF (128 * GA_LDA)              // 4608 floats
#define GB_BUF (32 * GB_LDB)               // 4352 floats
#define GEMM_SMEM_BYTES ((2 * GA_BUF + 2 * GB_BUF) * 4)   // 71680 B

__device__ __forceinline__ float to_tf32(float x) {
    unsigned u;
    asm("cvt.rna.tf32.f32 %0, %1;" : "=r"(u) : "f"(x));
    return __uint_as_float(u);
}

__device__ __forceinline__ void mma_tf32(float& d0, float& d1, float& d2, float& d3,
                                         unsigned a0, unsigned a1, unsigned a2, unsigned a3,
                                         unsigned b0, unsigned b1)
{
    asm volatile("mma.sync.aligned.m16n8k8.row.col.f32.tf32.tf32.f32 "
                 "{%0,%1,%2,%3}, {%4,%5,%6,%7}, {%8,%9}, {%0,%1,%2,%3};"
                 : "+f"(d0), "+f"(d1), "+f"(d2), "+f"(d3)
                 : "r"(a0), "r"(a1), "r"(a2), "r"(a3), "r"(b0), "r"(b1));
}

__global__ __launch_bounds__(256)
void sgemm_tf32(const float* __restrict__ A, const float* __restrict__ Bm,
                const float* __restrict__ bias, float* __restrict__ C,
                int M, int N, int K, int relu)
{
    extern __shared__ float sm[];
    float* As = sm;                  // [2][128][GA_LDA]
    float* Bs = sm + 2 * GA_BUF;     // [2][32][GB_LDB]

    const int tid  = threadIdx.x;
    const int bm   = blockIdx.y * 128;
    const int bn   = blockIdx.x * 128;
    const int lane = tid & 31;
    const int wid  = tid >> 5;
    const int wm0  = (wid & 1) * 64;        // warp m offset (2 warps along m)
    const int wn0  = (wid >> 1) * 32;       // warp n offset (4 warps along n)
    const int g    = lane >> 2;             // groupID 0..7
    const int tig  = lane & 3;              // thread-in-group 0..3

    // producer indices (both coalesced LDG, conflict-free STS)
    const int ar  = tid >> 3;               // A row 0..31 (+32 per it)
    const int ac4 = (tid & 7) * 4;          // A k-offset 0..28
    const int bk  = tid >> 3;               // B k row 0..31
    const int bc0 = tid & 7;                // B n-chunk 0..7 (+8 per it)

    float acc[4][4][4];
#pragma unroll
    for (int mt = 0; mt < 4; mt++)
#pragma unroll
        for (int nt = 0; nt < 4; nt++)
#pragma unroll
            for (int r = 0; r < 4; r++) acc[mt][nt][r] = 0.f;

    float4 pa[4], pb[4];

    // ---- preload k0 = 0 ----
#pragma unroll
    for (int it = 0; it < 4; it++) {
        pa[it] = *(const float4*)(A  + (size_t)(bm + ar + it * 32) * K + ac4);
        pb[it] = *(const float4*)(Bm + (size_t)bk * N + bn + (bc0 + it * 8) * 4);
    }
#pragma unroll
    for (int it = 0; it < 4; it++) {
        float4 v = pa[it];
        float4 w; w.x = to_tf32(v.x); w.y = to_tf32(v.y); w.z = to_tf32(v.z); w.w = to_tf32(v.w);
        *(float4*)(As + (ar + it * 32) * GA_LDA + ac4) = w;
        v = pb[it];
        w.x = to_tf32(v.x); w.y = to_tf32(v.y); w.z = to_tf32(v.z); w.w = to_tf32(v.w);
        *(float4*)(Bs + bk * GB_LDB + (bc0 + it * 8) * 4) = w;
    }
    __syncthreads();

    int buf = 0;
    for (int k0 = 0; k0 < K; k0 += 32) {
        const int kn = k0 + 32;
        if (kn < K) {
#pragma unroll
            for (int it = 0; it < 4; it++) {
                pa[it] = *(const float4*)(A  + (size_t)(bm + ar + it * 32) * K + kn + ac4);
                pb[it] = *(const float4*)(Bm + (size_t)(kn + bk) * N + bn + (bc0 + it * 8) * 4);
            }
        }

        const float* Ab = As + buf * GA_BUF;
        const float* Bb = Bs + buf * GB_BUF;
#pragma unroll
        for (int ks = 0; ks < 4; ks++) {
            unsigned bfr[4][2];
#pragma unroll
            for (int nt = 0; nt < 4; nt++) {
                const float* bp = Bb + (ks * 8 + tig) * GB_LDB + wn0 + nt * 8 + g;
                bfr[nt][0] = __float_as_uint(bp[0]);
                bfr[nt][1] = __float_as_uint(bp[4 * GB_LDB]);
            }
#pragma unroll
            for (int mt = 0; mt < 4; mt++) {
                const float* ap = Ab + (wm0 + mt * 16 + g) * GA_LDA + ks * 8 + tig;
                unsigned a0 = __float_as_uint(ap[0]);
                unsigned a1 = __float_as_uint(ap[8 * GA_LDA]);
                unsigned a2 = __float_as_uint(ap[4]);
                unsigned a3 = __float_as_uint(ap[8 * GA_LDA + 4]);
#pragma unroll
                for (int nt = 0; nt < 4; nt++)
                    mma_tf32(acc[mt][nt][0], acc[mt][nt][1], acc[mt][nt][2], acc[mt][nt][3],
                             a0, a1, a2, a3, bfr[nt][0], bfr[nt][1]);
            }
        }

        if (kn < K) {
            const int nb = buf ^ 1;
            float* Ad = As + nb * GA_BUF;
            float* Bd = Bs + nb * GB_BUF;
#pragma unroll
            for (int it = 0; it < 4; it++) {
                float4 v = pa[it];
                float4 w; w.x = to_tf32(v.x); w.y = to_tf32(v.y); w.z = to_tf32(v.z); w.w = to_tf32(v.w);
                *(float4*)(Ad + (ar + it * 32) * GA_LDA + ac4) = w;
                v = pb[it];
                w.x = to_tf32(v.x); w.y = to_tf32(v.y); w.z = to_tf32(v.z); w.w = to_tf32(v.w);
                *(float4*)(Bd + bk * GB_LDB + (bc0 + it * 8) * 4) = w;
            }
            __syncthreads();
            buf = nb;
        }
    }

    // ---- epilogue: bias (+ReLU), float2 stores ----
#pragma unroll
    for (int mt = 0; mt < 4; mt++) {
        const int row = bm + wm0 + mt * 16 + g;
#pragma unroll
        for (int nt = 0; nt < 4; nt++) {
            const int col = bn + wn0 + nt * 8 + 2 * tig;
            const float b0v = bias[col], b1v = bias[col + 1];
            float v0 = acc[mt][nt][0] + b0v;
            float v1 = acc[mt][nt][1] + b1v;
            float v2 = acc[mt][nt][2] + b0v;
            float v3 = acc[mt][nt][3] + b1v;
            if (relu) {
                v0 = fmaxf(v0, 0.f); v1 = fmaxf(v1, 0.f);
                v2 = fmaxf(v2, 0.f); v3 = fmaxf(v3, 0.f);
            }
            float2 o0; o0.x = v0; o0.y = v1;
            float2 o1; o1.x = v2; o1.y = v3;
            *(float2*)(C + (size_t)row * N + col)       = o0;
            *(float2*)(C + (size_t)(row + 8) * N + col) = o1;
        }
    }
}

// ============================================================================
// Fused sparse attention (flash-style) — unchanged from passing kernel.
// ============================================================================
constexpr int ATTN_SMEM_BYTES = (64 * 64 + 64 * 68 + 64 * 64) * 4;  // 50176

__global__ __launch_bounds__(128)
void attn_kernel(const float* __restrict__ qkv, float* __restrict__ out)
{
    constexpr int L = SEQ, Pp = PLEN, D = DMODEL, DH = DHEAD;
    constexpr int QT = 64, KT = 64, KLD = 68;
    extern __shared__ float sm[];
    float* Qs  = sm;                 // [DH][QT]
    float* KPs = sm + DH * QT;       // [DH][KLD] (K^T), reused as P [KT][KLD]
    float* Vs  = KPs + DH * KLD;     // [KT][DH]

    const int tid = threadIdx.x;
    const int l0  = blockIdx.x * QT;
    const int b   = blockIdx.y >> 3;
    const int h   = blockIdx.y & 7;
    const int rg  = tid >> 3;        // 0..15
    const int cg  = tid & 7;         // 0..7

    const float* qbase = qkv + ((size_t)b * L) * (3 * D) + h * DH;
    const float* kbase = qbase + D;
    const float* vbase = qbase + 2 * D;

#pragma unroll
    for (int it = 0; it < 8; it++) {
        int idx = tid + it * 128;
        int r = idx >> 4;
        int c = (idx & 15) << 2;
        float4 q4 = *(const float4*)(qbase + (size_t)(l0 + r) * (3 * D) + c);
        Qs[(c + 0) * QT + r] = q4.x * 0.125f;
        Qs[(c + 1) * QT + r] = q4.y * 0.125f;
        Qs[(c + 2) * QT + r] = q4.z * 0.125f;
        Qs[(c + 3) * QT + r] = q4.w * 0.125f;
    }

    float mrow[4], lrow[4], acc[4][8];
#pragma unroll
    for (int i = 0; i < 4; i++) {
        mrow[i] = -1e30f; lrow[i] = 0.f;
#pragma unroll
        for (int j = 0; j < 8; j++) acc[i][j] = 0.f;
    }
    __syncthreads();

    for (int kc = 0; kc < Pp; kc += KT) {
#pragma unroll
        for (int it = 0; it < 8; it++) {
            int idx = tid + it * 128;
            int r = idx >> 4;
            int c = (idx & 15) << 2;
            float4 k4 = *(const float4*)(kbase + (size_t)(kc + r) * (3 * D) + c);
            KPs[(c + 0) * KLD + r] = k4.x;
            KPs[(c + 1) * KLD + r] = k4.y;
            KPs[(c + 2) * KLD + r] = k4.z;
            KPs[(c + 3) * KLD + r] = k4.w;
            float4 v4 = *(const float4*)(vbase + (size_t)(kc + r) * (3 * D) + c);
            *(float4*)(Vs + r * DH + c) = v4;
        }
        __syncthreads();

        float s[4][8];
#pragma unroll
        for (int i = 0; i < 4; i++)
#pragma unroll
            for (int j = 0; j < 8; j++) s[i][j] = 0.f;
#pragma unroll 8
        for (int kk = 0; kk < DH; kk++) {
            float a[4], bv[8];
            *(float4*)a        = *(const float4*)(Qs  + kk * QT  + rg * 4);
            *(float4*)bv       = *(const float4*)(KPs + kk * KLD + cg * 8);
            *(float4*)(bv + 4) = *(const float4*)(KPs + kk * KLD + cg * 8 + 4);
#pragma unroll
            for (int i = 0; i < 4; i++)
#pragma unroll
                for (int j = 0; j < 8; j++)
                    s[i][j] = fmaf(a[i], bv[j], s[i][j]);
        }
        __syncthreads();

#pragma unroll
        for (int i = 0; i < 4; i++) {
            float rmax = s[i][0];
#pragma unroll
            for (int j = 1; j < 8; j++) rmax = fmaxf(rmax, s[i][j]);
            rmax = fmaxf(rmax, __shfl_xor_sync(0xffffffffu, rmax, 1));
            rmax = fmaxf(rmax, __shfl_xor_sync(0xffffffffu, rmax, 2));
            rmax = fmaxf(rmax, __shfl_xor_sync(0xffffffffu, rmax, 4));
            float mnew = fmaxf(mrow[i], rmax);
            float corr = __expf(mrow[i] - mnew);
            mrow[i] = mnew;
            float p[8], rs = 0.f;
#pragma unroll
            for (int j = 0; j < 8; j++) { p[j] = __expf(s[i][j] - mnew); rs += p[j]; }
            rs += __shfl_xor_sync(0xffffffffu, rs, 1);
            rs += __shfl_xor_sync(0xffffffffu, rs, 2);
            rs += __shfl_xor_sync(0xffffffffu, rs, 4);
            lrow[i] = lrow[i] * corr + rs;
#pragma unroll
            for (int j = 0; j < 8; j++) {
                acc[i][j] *= corr;
                KPs[(cg * 8 + j) * KLD + rg * 4 + i] = p[j];
            }
        }
        __syncthreads();

#pragma unroll 8
        for (int kk = 0; kk < KT; kk++) {
            float a[4], bv[8];
            *(float4*)a        = *(const float4*)(KPs + kk * KLD + rg * 4);
            *(float4*)bv       = *(const float4*)(Vs  + kk * DH  + cg * 8);
            *(float4*)(bv + 4) = *(const float4*)(Vs  + kk * DH  + cg * 8 + 4);
#pragma unroll
            for (int i = 0; i < 4; i++)
#pragma unroll
                for (int j = 0; j < 8; j++)
                    acc[i][j] = fmaf(a[i], bv[j], acc[i][j]);
        }
        __syncthreads();
    }

    const bool isgen = (l0 >= Pp);
#pragma unroll
    for (int i = 0; i < 4; i++) {
        const int r  = rg * 4 + i;
        const int lq = l0 + r;
        if (isgen) {
            const float* ks = kbase + (size_t)lq * (3 * D);
            float part = 0.f;
#pragma unroll
            for (int kk2 = 0; kk2 < 8; kk2++) {
                int k = cg * 8 + kk2;
                part += Qs[k * QT + r] * ks[k];
            }
            part += __shfl_xor_sync(0xffffffffu, part, 1);
            part += __shfl_xor_sync(0xffffffffu, part, 2);
            part += __shfl_xor_sync(0xffffffffu, part, 4);
            const float dlog = part;
            float mnew = fmaxf(mrow[i], dlog);
            float corr = __expf(mrow[i] - mnew);
            float ed   = __expf(dlog - mnew);
            lrow[i] = lrow[i] * corr + ed;
            const float* vs = vbase + (size_t)lq * (3 * D) + cg * 8;
            float4 v0 = *(const float4*)(vs);
            float4 v1 = *(const float4*)(vs + 4);
            float vv[8] = {v0.x, v0.y, v0.z, v0.w, v1.x, v1.y, v1.z, v1.w};
#pragma unroll
            for (int j = 0; j < 8; j++)
                acc[i][j] = acc[i][j] * corr + ed * vv[j];
        }
        const float inv = 1.f / lrow[i];
        float* op = out + ((size_t)b * L + lq) * D + h * DH + cg * 8;
        float4 o0, o1;
        o0.x = acc[i][0] * inv; o0.y = acc[i][1] * inv;
        o0.z = acc[i][2] * inv; o0.w = acc[i][3] * inv;
        o1.x = acc[i][4] * inv; o1.y = acc[i][5] * inv;
        o1.z = acc[i][6] * inv; o1.w = acc[i][7] * inv;
        *(float4*)op       = o0;
        *(float4*)(op + 4) = o1;
    }
}

// ============================================================================
// Fused residual add + LayerNorm (in-place on x): x = LN(x + delta)*g + b
// ============================================================================
__global__ __launch_bounds__(128)
void add_ln_kernel(float* __restrict__ x, const float* __restrict__ delta,
                   const float* __restrict__ gamma, const float* __restrict__ beta)
{
    __shared__ float rs[4], rq[4];
    const int tid = threadIdx.x;
    const size_t off = (size_t)blockIdx.x * DMODEL + tid * 4;
    float4 a  = *(const float4*)(x + off);
    float4 d4 = *(const float4*)(delta + off);
    float v0 = a.x + d4.x, v1 = a.y + d4.y, v2 = a.z + d4.z, v3 = a.w + d4.w;
    float s = v0 + v1 + v2 + v3;
    float q = v0 * v0 + v1 * v1 + v2 * v2 + v3 * v3;
#pragma unroll
    for (int o = 16; o > 0; o >>= 1) {
        s += __shfl_xor_sync(0xffffffffu, s, o);
        q += __shfl_xor_sync(0xffffffffu, q, o);
    }
    if ((tid & 31) == 0) { rs[tid >> 5] = s; rq[tid >> 5] = q; }
    __syncthreads();
    const float ts = rs[0] + rs[1] + rs[2] + rs[3];
    const float tq = rq[0] + rq[1] + rq[2] + rq[3];
    const float mu   = ts * (1.0f / DMODEL);
    const float var  = tq * (1.0f / DMODEL) - mu * mu;
    const float rstd = rsqrtf(var + 1e-5f);
    float4 g4 = *(const float4*)(gamma + tid * 4);
    float4 b4 = *(const float4*)(beta + tid * 4);
    float4 o;
    o.x = (v0 - mu) * rstd * g4.x + b4.x;
    o.y = (v1 - mu) * rstd * g4.y + b4.y;
    o.z = (v2 - mu) * rstd * g4.z + b4.z;
    o.w = (v3 - mu) * rstd * g4.w + b4.w;
    *(float4*)(x + off) = o;
}

// ============================================================================
// Concat pcpt/gen into x; split x into (pcpt_out, gen_out) at the end.
// ============================================================================
__global__ void concat_in_kernel(const float* __restrict__ pcpt,
                                 const float* __restrict__ gen,
                                 float* __restrict__ x)
{
    const size_t i = (size_t)blockIdx.x * blockDim.x + threadIdx.x;
    const size_t row = i >> 7;
    const int    c4  = (int)(i & 127);
    const size_t b   = row >> 11;
    const int    l   = (int)(row & 2047);
    const float4* src;
    if (l < PLEN) src = (const float4*)pcpt + ((b * PLEN + l) * 128 + c4);
    else          src = (const float4*)gen  + ((b * PLEN + (l - PLEN)) * 128 + c4);
    ((float4*)x)[i] = *src;
}

__global__ void split_out_kernel(const float* __restrict__ x, float* __restrict__ out)
{
    const size_t i = (size_t)blockIdx.x * blockDim.x + threadIdx.x;
    const size_t row = i >> 7;
    const int    c4  = (int)(i & 127);
    const size_t b   = row >> 11;
    const int    l   = (int)(row & 2047);
    size_t dst;
    if (l < PLEN) dst = (b * PLEN + l) * 128 + c4;
    else          dst = (size_t)BSZ * PLEN * 128 + (b * PLEN + (l - PLEN)) * 128 + c4;
    ((float4*)out)[dst] = ((const float4*)x)[i];
}

// ============================================================================
// kernel_launch
// ============================================================================
extern "C" void kernel_launch(void* const* d_in, const int* in_sizes, int n_in,
                              void* d_out, int out_size)
{
    (void)in_sizes; (void)n_in; (void)out_size;
    const float* pcpt = (const float*)d_in[0];
    const float* gen  = (const float*)d_in[1];
    const float* Wqkv = (const float*)d_in[3];
    const float* bqkv = (const float*)d_in[4];
    const float* Wo   = (const float*)d_in[5];
    const float* bo   = (const float*)d_in[6];
    const float* W1   = (const float*)d_in[7];
    const float* b1   = (const float*)d_in[8];
    const float* W2   = (const float*)d_in[9];
    const float* b2   = (const float*)d_in[10];
    const float* g1   = (const float*)d_in[11];
    const float* be1  = (const float*)d_in[12];
    const float* g2   = (const float*)d_in[13];
    const float* be2  = (const float*)d_in[14];
    float* out = (float*)d_out;

    float *x, *qkvb, *attnb, *hid;
    cudaGetSymbolAddress((void**)&x,     g_x);
    cudaGetSymbolAddress((void**)&qkvb,  g_qkv);
    cudaGetSymbolAddress((void**)&attnb, g_attn);
    cudaGetSymbolAddress((void**)&hid,   g_hid);

    cudaFuncSetAttribute((const void*)attn_kernel,
                         cudaFuncAttributeMaxDynamicSharedMemorySize,
                         ATTN_SMEM_BYTES);
    cudaFuncSetAttribute((const void*)sgemm_tf32,
                         cudaFuncAttributeMaxDynamicSharedMemorySize,
                         GEMM_SMEM_BYTES);

    const int total4 = MROWS * DMODEL / 4;
    concat_in_kernel<<<total4 / 256, 256>>>(pcpt, gen, x);

    constexpr int M = MROWS;
    for (int layer = 0; layer < NLAYER; layer++) {
        const float* wq  = Wqkv + (size_t)layer * DMODEL * 3 * DMODEL;
        const float* bq  = bqkv + (size_t)layer * 3 * DMODEL;
        const float* wo  = Wo   + (size_t)layer * DMODEL * DMODEL;
        const float* bob = bo   + (size_t)layer * DMODEL;
        const float* w1  = W1   + (size_t)layer * DMODEL * DFF;
        const float* b1b = b1   + (size_t)layer * DFF;
        const float* w2  = W2   + (size_t)layer * DFF * DMODEL;
        const float* b2b = b2   + (size_t)layer * DMODEL;

        // 1) qkv = x @ Wqkv + bqkv               (8192 x 1536, K=512)
        sgemm_tf32<<<dim3(3 * DMODEL / 128, M / 128), 256, GEMM_SMEM_BYTES>>>(
            x, wq, bq, qkvb, M, 3 * DMODEL, DMODEL, 0);

        // 2) fused sparse attention -> attnb
        attn_kernel<<<dim3(SEQ / 64, BSZ * NH), 128, ATTN_SMEM_BYTES>>>(qkvb, attnb);

        // 3) proj = attn @ Wo + bo -> hid (tmp)  (8192 x 512, K=512)
        sgemm_tf32<<<dim3(DMODEL / 128, M / 128), 256, GEMM_SMEM_BYTES>>>(
            attnb, wo, bob, hid, M, DMODEL, DMODEL, 0);

        // 4) x = LN(x + proj)
        add_ln_kernel<<<MROWS, 128>>>(x, hid, g1 + layer * DMODEL, be1 + layer * DMODEL);

        // 5) hid = relu(x @ W1 + b1)             (8192 x 2048, K=512)
        sgemm_tf32<<<dim3(DFF / 128, M / 128), 256, GEMM_SMEM_BYTES>>>(
            x, w1, b1b, hid, M, DFF, DMODEL, 1);

        // 6) attnb = hid @ W2 + b2               (8192 x 512, K=2048)
        sgemm_tf32<<<dim3(DMODEL / 128, M / 128), 256, GEMM_SMEM_BYTES>>>(
            hid, w2, b2b, attnb, M, DMODEL, DFF, 0);

        // 7) x = LN(x + ffn)
        add_ln_kernel<<<MROWS, 128>>>(x, attnb, g2 + layer * DMODEL, be2 + layer * DMODEL);
    }

    split_out_kernel<<<total4 / 256, 256>>>(x, out);
}

// round 14
// speedup vs baseline: 1.8516x; 1.0019x over previous
#include <cuda_runtime.h>

// ---------------- problem constants ----------------
#define NLAYER 4
#define BSZ    4
#define SEQ    2048
#define PLEN   1024
#define DMODEL 512
#define DFF    2048
#define NH     8
#define DHEAD  64
#define MROWS  (BSZ * SEQ)      // 8192 token rows

// ---------------- scratch (device globals: no allocation allowed) ----------
__device__ float g_x   [(size_t)MROWS * DMODEL];       // 16 MB residual stream
__device__ float g_qkv [(size_t)MROWS * 3 * DMODEL];   // 48 MB qkv
__device__ float g_attn[(size_t)MROWS * DMODEL];       // 16 MB attn out / ffn2 out
__device__ float g_hid [(size_t)MROWS * DFF];          // 64 MB ffn hidden / proj tmp

// ============================================================================
// TF32 tensor-core SGEMM: C[M,N] = A[M,K] @ B[K,N] + bias[N], optional ReLU.
// 128x128x32 tile, 256 threads (8 warps, 2x4), warp tile 64x32 via m16n8k8.
// A smem [128][36] (lda=36 -> conflict-free frag LDS), B smem [32][136].
// Inputs rounded to tf32 with cvt.rna in the producer path.
// ============================================================================
#define GA_LDA 36
#define GB_LDB 136
#define GA_BUF (128 * GA_LDA)              // 4608 floats
#define GB_BUF (32 * GB_LDB)               // 4352 floats
#define GEMM_SMEM_BYTES ((2 * GA_BUF + 2 * GB_BUF) * 4)   // 71680 B

__device__ __forceinline__ float to_tf32(float x) {
    unsigned u;
    asm("cvt.rna.tf32.f32 %0, %1;" : "=r"(u) : "f"(x));
    return __uint_as_float(u);
}

__device__ __forceinline__ void mma_tf32(float& d0, float& d1, float& d2, float& d3,
                                         unsigned a0, unsigned a1, unsigned a2, unsigned a3,
                                         unsigned b0, unsigned b1)
{
    asm volatile("mma.sync.aligned.m16n8k8.row.col.f32.tf32.tf32.f32 "
                 "{%0,%1,%2,%3}, {%4,%5,%6,%7}, {%8,%9}, {%0,%1,%2,%3};"
                 : "+f"(d0), "+f"(d1), "+f"(d2), "+f"(d3)
                 : "r"(a0), "r"(a1), "r"(a2), "r"(a3), "r"(b0), "r"(b1));
}

__global__ __launch_bounds__(256)
void sgemm_tf32(const float* __restrict__ A, const float* __restrict__ Bm,
                const float* __restrict__ bias, float* __restrict__ C,
                int M, int N, int K, int relu)
{
    extern __shared__ float sm[];
    float* As = sm;                  // [2][128][GA_LDA]
    float* Bs = sm + 2 * GA_BUF;     // [2][32][GB_LDB]

    const int tid  = threadIdx.x;
    const int bm   = blockIdx.y * 128;
    const int bn   = blockIdx.x * 128;
    const int lane = tid & 31;
    const int wid  = tid >> 5;
    const int wm0  = (wid & 1) * 64;        // warp m offset (2 warps along m)
    const int wn0  = (wid >> 1) * 32;       // warp n offset (4 warps along n)
    const int g    = lane >> 2;             // groupID 0..7
    const int tig  = lane & 3;              // thread-in-group 0..3

    // producer indices (both coalesced LDG, conflict-free STS)
    const int ar  = tid >> 3;               // A row 0..31 (+32 per it)
    const int ac4 = (tid & 7) * 4;          // A k-offset 0..28
    const int bk  = tid >> 3;               // B k row 0..31
    const int bc0 = tid & 7;                // B n-chunk 0..7 (+8 per it)

    float acc[4][4][4];
#pragma unroll
    for (int mt = 0; mt < 4; mt++)
#pragma unroll
        for (int nt = 0; nt < 4; nt++)
#pragma unroll
            for (int r = 0; r < 4; r++) acc[mt][nt][r] = 0.f;

    float4 pa[4], pb[4];

    // ---- preload k0 = 0 ----
#pragma unroll
    for (int it = 0; it < 4; it++) {
        pa[it] = *(const float4*)(A  + (size_t)(bm + ar + it * 32) * K + ac4);
        pb[it] = *(const float4*)(Bm + (size_t)bk * N + bn + (bc0 + it * 8) * 4);
    }
#pragma unroll
    for (int it = 0; it < 4; it++) {
        float4 v = pa[it];
        float4 w; w.x = to_tf32(v.x); w.y = to_tf32(v.y); w.z = to_tf32(v.z); w.w = to_tf32(v.w);
        *(float4*)(As + (ar + it * 32) * GA_LDA + ac4) = w;
        v = pb[it];
        w.x = to_tf32(v.x); w.y = to_tf32(v.y); w.z = to_tf32(v.z); w.w = to_tf32(v.w);
        *(float4*)(Bs + bk * GB_LDB + (bc0 + it * 8) * 4) = w;
    }
    __syncthreads();

    int buf = 0;
    for (int k0 = 0; k0 < K; k0 += 32) {
        const int kn = k0 + 32;
        if (kn < K) {
#pragma unroll
            for (int it = 0; it < 4; it++) {
                pa[it] = *(const float4*)(A  + (size_t)(bm + ar + it * 32) * K + kn + ac4);
                pb[it] = *(const float4*)(Bm + (size_t)(kn + bk) * N + bn + (bc0 + it * 8) * 4);
            }
        }

        const float* Ab = As + buf * GA_BUF;
        const float* Bb = Bs + buf * GB_BUF;
#pragma unroll
        for (int ks = 0; ks < 4; ks++) {
            unsigned bfr[4][2];
#pragma unroll
            for (int nt = 0; nt < 4; nt++) {
                const float* bp = Bb + (ks * 8 + tig) * GB_LDB + wn0 + nt * 8 + g;
                bfr[nt][0] = __float_as_uint(bp[0]);
                bfr[nt][1] = __float_as_uint(bp[4 * GB_LDB]);
            }
#pragma unroll
            for (int mt = 0; mt < 4; mt++) {
                const float* ap = Ab + (wm0 + mt * 16 + g) * GA_LDA + ks * 8 + tig;
                unsigned a0 = __float_as_uint(ap[0]);
                unsigned a1 = __float_as_uint(ap[8 * GA_LDA]);
                unsigned a2 = __float_as_uint(ap[4]);
                unsigned a3 = __float_as_uint(ap[8 * GA_LDA + 4]);
#pragma unroll
                for (int nt = 0; nt < 4; nt++)
                    mma_tf32(acc[mt][nt][0], acc[mt][nt][1], acc[mt][nt][2], acc[mt][nt][3],
                             a0, a1, a2, a3, bfr[nt][0], bfr[nt][1]);
            }
        }

        if (kn < K) {
            const int nb = buf ^ 1;
            float* Ad = As + nb * GA_BUF;
            float* Bd = Bs + nb * GB_BUF;
#pragma unroll
            for (int it = 0; it < 4; it++) {
                float4 v = pa[it];
                float4 w; w.x = to_tf32(v.x); w.y = to_tf32(v.y); w.z = to_tf32(v.z); w.w = to_tf32(v.w);
                *(float4*)(Ad + (ar + it * 32) * GA_LDA + ac4) = w;
                v = pb[it];
                w.x = to_tf32(v.x); w.y = to_tf32(v.y); w.z = to_tf32(v.z); w.w = to_tf32(v.w);
                *(float4*)(Bd + bk * GB_LDB + (bc0 + it * 8) * 4) = w;
            }
            __syncthreads();
            buf = nb;
        }
    }

    // ---- epilogue: bias (+ReLU), float2 stores ----
#pragma unroll
    for (int mt = 0; mt < 4; mt++) {
        const int row = bm + wm0 + mt * 16 + g;
#pragma unroll
        for (int nt = 0; nt < 4; nt++) {
            const int col = bn + wn0 + nt * 8 + 2 * tig;
            const float b0v = bias[col], b1v = bias[col + 1];
            float v0 = acc[mt][nt][0] + b0v;
            float v1 = acc[mt][nt][1] + b1v;
            float v2 = acc[mt][nt][2] + b0v;
            float v3 = acc[mt][nt][3] + b1v;
            if (relu) {
                v0 = fmaxf(v0, 0.f); v1 = fmaxf(v1, 0.f);
                v2 = fmaxf(v2, 0.f); v3 = fmaxf(v3, 0.f);
            }
            float2 o0; o0.x = v0; o0.y = v1;
            float2 o1; o1.x = v2; o1.y = v3;
            *(float2*)(C + (size_t)row * N + col)       = o0;
            *(float2*)(C + (size_t)(row + 8) * N + col) = o1;
        }
    }
}

// ============================================================================
// Fused sparse attention (flash-style) — unchanged from passing kernel.
// ============================================================================
constexpr int ATTN_SMEM_BYTES = (64 * 64 + 64 * 68 + 64 * 64) * 4;  // 50176

__global__ __launch_bounds__(128)
void attn_kernel(const float* __restrict__ qkv, float* __restrict__ out)
{
    constexpr int L = SEQ, Pp = PLEN, D = DMODEL, DH = DHEAD;
    constexpr int QT = 64, KT = 64, KLD = 68;
    extern __shared__ float sm[];
    float* Qs  = sm;                 // [DH][QT]
    float* KPs = sm + DH * QT;       // [DH][KLD] (K^T), reused as P [KT][KLD]
    float* Vs  = KPs + DH * KLD;     // [KT][DH]

    const int tid = threadIdx.x;
    const int l0  = blockIdx.x * QT;
    const int b   = blockIdx.y >> 3;
    const int h   = blockIdx.y & 7;
    const int rg  = tid >> 3;        // 0..15
    const int cg  = tid & 7;         // 0..7

    const float* qbase = qkv + ((size_t)b * L) * (3 * D) + h * DH;
    const float* kbase = qbase + D;
    const float* vbase = qbase + 2 * D;

#pragma unroll
    for (int it = 0; it < 8; it++) {
        int idx = tid + it * 128;
        int r = idx >> 4;
        int c = (idx & 15) << 2;
        float4 q4 = *(const float4*)(qbase + (size_t)(l0 + r) * (3 * D) + c);
        Qs[(c + 0) * QT + r] = q4.x * 0.125f;
        Qs[(c + 1) * QT + r] = q4.y * 0.125f;
        Qs[(c + 2) * QT + r] = q4.z * 0.125f;
        Qs[(c + 3) * QT + r] = q4.w * 0.125f;
    }

    float mrow[4], lrow[4], acc[4][8];
#pragma unroll
    for (int i = 0; i < 4; i++) {
        mrow[i] = -1e30f; lrow[i] = 0.f;
#pragma unroll
        for (int j = 0; j < 8; j++) acc[i][j] = 0.f;
    }
    __syncthreads();

    for (int kc = 0; kc < Pp; kc += KT) {
#pragma unroll
        for (int it = 0; it < 8; it++) {
            int idx = tid + it * 128;
            int r = idx >> 4;
            int c = (idx & 15) << 2;
            float4 k4 = *(const float4*)(kbase + (size_t)(kc + r) * (3 * D) + c);
            KPs[(c + 0) * KLD + r] = k4.x;
            KPs[(c + 1) * KLD + r] = k4.y;
            KPs[(c + 2) * KLD + r] = k4.z;
            KPs[(c + 3) * KLD + r] = k4.w;
            float4 v4 = *(const float4*)(vbase + (size_t)(kc + r) * (3 * D) + c);
            *(float4*)(Vs + r * DH + c) = v4;
        }
        __syncthreads();

        float s[4][8];
#pragma unroll
        for (int i = 0; i < 4; i++)
#pragma unroll
            for (int j = 0; j < 8; j++) s[i][j] = 0.f;
#pragma unroll 8
        for (int kk = 0; kk < DH; kk++) {
            float a[4], bv[8];
            *(float4*)a        = *(const float4*)(Qs  + kk * QT  + rg * 4);
            *(float4*)bv       = *(const float4*)(KPs + kk * KLD + cg * 8);
            *(float4*)(bv + 4) = *(const float4*)(KPs + kk * KLD + cg * 8 + 4);
#pragma unroll
            for (int i = 0; i < 4; i++)
#pragma unroll
                for (int j = 0; j < 8; j++)
                    s[i][j] = fmaf(a[i], bv[j], s[i][j]);
        }
        __syncthreads();

#pragma unroll
        for (int i = 0; i < 4; i++) {
            float rmax = s[i][0];
#pragma unroll
            for (int j = 1; j < 8; j++) rmax = fmaxf(rmax, s[i][j]);
            rmax = fmaxf(rmax, __shfl_xor_sync(0xffffffffu, rmax, 1));
            rmax = fmaxf(rmax, __shfl_xor_sync(0xffffffffu, rmax, 2));
            rmax = fmaxf(rmax, __shfl_xor_sync(0xffffffffu, rmax, 4));
            float mnew = fmaxf(mrow[i], rmax);
            float corr = __expf(mrow[i] - mnew);
            mrow[i] = mnew;
            float p[8], rs = 0.f;
#pragma unroll
            for (int j = 0; j < 8; j++) { p[j] = __expf(s[i][j] - mnew); rs += p[j]; }
            rs += __shfl_xor_sync(0xffffffffu, rs, 1);
            rs += __shfl_xor_sync(0xffffffffu, rs, 2);
            rs += __shfl_xor_sync(0xffffffffu, rs, 4);
            lrow[i] = lrow[i] * corr + rs;
#pragma unroll
            for (int j = 0; j < 8; j++) {
                acc[i][j] *= corr;
                KPs[(cg * 8 + j) * KLD + rg * 4 + i] = p[j];
            }
        }
        __syncthreads();

#pragma unroll 8
        for (int kk = 0; kk < KT; kk++) {
            float a[4], bv[8];
            *(float4*)a        = *(const float4*)(KPs + kk * KLD + rg * 4);
            *(float4*)bv       = *(const float4*)(Vs  + kk * DH  + cg * 8);
            *(float4*)(bv + 4) = *(const float4*)(Vs  + kk * DH  + cg * 8 + 4);
#pragma unroll
            for (int i = 0; i < 4; i++)
#pragma unroll
                for (int j = 0; j < 8; j++)
                    acc[i][j] = fmaf(a[i], bv[j], acc[i][j]);
        }
        __syncthreads();
    }

    const bool isgen = (l0 >= Pp);
#pragma unroll
    for (int i = 0; i < 4; i++) {
        const int r  = rg * 4 + i;
        const int lq = l0 + r;
        if (isgen) {
            const float* ks = kbase + (size_t)lq * (3 * D);
            float part = 0.f;
#pragma unroll
            for (int kk2 = 0; kk2 < 8; kk2++) {
                int k = cg * 8 + kk2;
                part += Qs[k * QT + r] * ks[k];
            }
            part += __shfl_xor_sync(0xffffffffu, part, 1);
            part += __shfl_xor_sync(0xffffffffu, part, 2);
            part += __shfl_xor_sync(0xffffffffu, part, 4);
            const float dlog = part;
            float mnew = fmaxf(mrow[i], dlog);
            float corr = __expf(mrow[i] - mnew);
            float ed   = __expf(dlog - mnew);
            lrow[i] = lrow[i] * corr + ed;
            const float* vs = vbase + (size_t)lq * (3 * D) + cg * 8;
            float4 v0 = *(const float4*)(vs);
            float4 v1 = *(const float4*)(vs + 4);
            float vv[8] = {v0.x, v0.y, v0.z, v0.w, v1.x, v1.y, v1.z, v1.w};
#pragma unroll
            for (int j = 0; j < 8; j++)
                acc[i][j] = acc[i][j] * corr + ed * vv[j];
        }
        const float inv = 1.f / lrow[i];
        float* op = out + ((size_t)b * L + lq) * D + h * DH + cg * 8;
        float4 o0, o1;
        o0.x = acc[i][0] * inv; o0.y = acc[i][1] * inv;
        o0.z = acc[i][2] * inv; o0.w = acc[i][3] * inv;
        o1.x = acc[i][4] * inv; o1.y = acc[i][5] * inv;
        o1.z = acc[i][6] * inv; o1.w = acc[i][7] * inv;
        *(float4*)op       = o0;
        *(float4*)(op + 4) = o1;
    }
}

// ============================================================================
// Fused residual add + LayerNorm (in-place on x): x = LN(x + delta)*g + b
// ============================================================================
__global__ __launch_bounds__(128)
void add_ln_kernel(float* __restrict__ x, const float* __restrict__ delta,
                   const float* __restrict__ gamma, const float* __restrict__ beta)
{
    __shared__ float rs[4], rq[4];
    const int tid = threadIdx.x;
    const size_t off = (size_t)blockIdx.x * DMODEL + tid * 4;
    float4 a  = *(const float4*)(x + off);
    float4 d4 = *(const float4*)(delta + off);
    float v0 = a.x + d4.x, v1 = a.y + d4.y, v2 = a.z + d4.z, v3 = a.w + d4.w;
    float s = v0 + v1 + v2 + v3;
    float q = v0 * v0 + v1 * v1 + v2 * v2 + v3 * v3;
#pragma unroll
    for (int o = 16; o > 0; o >>= 1) {
        s += __shfl_xor_sync(0xffffffffu, s, o);
        q += __shfl_xor_sync(0xffffffffu, q, o);
    }
    if ((tid & 31) == 0) { rs[tid >> 5] = s; rq[tid >> 5] = q; }
    __syncthreads();
    const float ts = rs[0] + rs[1] + rs[2] + rs[3];
    const float tq = rq[0] + rq[1] + rq[2] + rq[3];
    const float mu   = ts * (1.0f / DMODEL);
    const float var  = tq * (1.0f / DMODEL) - mu * mu;
    const float rstd = rsqrtf(var + 1e-5f);
    float4 g4 = *(const float4*)(gamma + tid * 4);
    float4 b4 = *(const float4*)(beta + tid * 4);
    float4 o;
    o.x = (v0 - mu) * rstd * g4.x + b4.x;
    o.y = (v1 - mu) * rstd * g4.y + b4.y;
    o.z = (v2 - mu) * rstd * g4.z + b4.z;
    o.w = (v3 - mu) * rstd * g4.w + b4.w;
    *(float4*)(x + off) = o;
}

// ============================================================================
// Concat pcpt/gen into x; split x into (pcpt_out, gen_out) at the end.
// ============================================================================
__global__ void concat_in_kernel(const float* __restrict__ pcpt,
                                 const float* __restrict__ gen,
                                 float* __restrict__ x)
{
    const size_t i = (size_t)blockIdx.x * blockDim.x + threadIdx.x;
    const size_t row = i >> 7;
    const int    c4  = (int)(i & 127);
    const size_t b   = row >> 11;
    const int    l   = (int)(row & 2047);
    const float4* src;
    if (l < PLEN) src = (const float4*)pcpt + ((b * PLEN + l) * 128 + c4);
    else          src = (const float4*)gen  + ((b * PLEN + (l - PLEN)) * 128 + c4);
    ((float4*)x)[i] = *src;
}

__global__ void split_out_kernel(const float* __restrict__ x, float* __restrict__ out)
{
    const size_t i = (size_t)blockIdx.x * blockDim.x + threadIdx.x;
    const size_t row = i >> 7;
    const int    c4  = (int)(i & 127);
    const size_t b   = row >> 11;
    const int    l   = (int)(row & 2047);
    size_t dst;
    if (l < PLEN) dst = (b * PLEN + l) * 128 + c4;
    else          dst = (size_t)BSZ * PLEN * 128 + (b * PLEN + (l - PLEN)) * 128 + c4;
    ((float4*)out)[dst] = ((const float4*)x)[i];
}

// ============================================================================
// kernel_launch
// ============================================================================
extern "C" void kernel_launch(void* const* d_in, const int* in_sizes, int n_in,
                              void* d_out, int out_size)
{
    (void)in_sizes; (void)n_in; (void)out_size;
    const float* pcpt = (const float*)d_in[0];
    const float* gen  = (const float*)d_in[1];
    const float* Wqkv = (const float*)d_in[3];
    const float* bqkv = (const float*)d_in[4];
    const float* Wo   = (const float*)d_in[5];
    const float* bo   = (const float*)d_in[6];
    const float* W1   = (const float*)d_in[7];
    const float* b1   = (const float*)d_in[8];
    const float* W2   = (const float*)d_in[9];
    const float* b2   = (const float*)d_in[10];
    const float* g1   = (const float*)d_in[11];
    const float* be1  = (const float*)d_in[12];
    const float* g2   = (const float*)d_in[13];
    const float* be2  = (const float*)d_in[14];
    float* out = (float*)d_out;

    float *x, *qkvb, *attnb, *hid;
    cudaGetSymbolAddress((void**)&x,     g_x);
    cudaGetSymbolAddress((void**)&qkvb,  g_qkv);
    cudaGetSymbolAddress((void**)&attnb, g_attn);
    cudaGetSymbolAddress((void**)&hid,   g_hid);

    cudaFuncSetAttribute((const void*)attn_kernel,
                         cudaFuncAttributeMaxDynamicSharedMemorySize,
                         ATTN_SMEM_BYTES);
    cudaFuncSetAttribute((const void*)sgemm_tf32,
                         cudaFuncAttributeMaxDynamicSharedMemorySize,
                         GEMM_SMEM_BYTES);

    const int total4 = MROWS * DMODEL / 4;
    concat_in_kernel<<<total4 / 256, 256>>>(pcpt, gen, x);

    constexpr int M = MROWS;
    for (int layer = 0; layer < NLAYER; layer++) {
        const float* wq  = Wqkv + (size_t)layer * DMODEL * 3 * DMODEL;
        const float* bq  = bqkv + (size_t)layer * 3 * DMODEL;
        const float* wo  = Wo   + (size_t)layer * DMODEL * DMODEL;
        const float* bob = bo   + (size_t)layer * DMODEL;
        const float* w1  = W1   + (size_t)layer * DMODEL * DFF;
        const float* b1b = b1   + (size_t)layer * DFF;
        const float* w2  = W2   + (size_t)layer * DFF * DMODEL;
        const float* b2b = b2   + (size_t)layer * DMODEL;

        // 1) qkv = x @ Wqkv + bqkv               (8192 x 1536, K=512)
        sgemm_tf32<<<dim3(3 * DMODEL / 128, M / 128), 256, GEMM_SMEM_BYTES>>>(
            x, wq, bq, qkvb, M, 3 * DMODEL, DMODEL, 0);

        // 2) fused sparse attention -> attnb
        attn_kernel<<<dim3(SEQ / 64, BSZ * NH), 128, ATTN_SMEM_BYTES>>>(qkvb, attnb);

        // 3) proj = attn @ Wo + bo -> hid (tmp)  (8192 x 512, K=512)
        sgemm_tf32<<<dim3(DMODEL / 128, M / 128), 256, GEMM_SMEM_BYTES>>>(
            attnb, wo, bob, hid, M, DMODEL, DMODEL, 0);

        // 4) x = LN(x + proj)
        add_ln_kernel<<<MROWS, 128>>>(x, hid, g1 + layer * DMODEL, be1 + layer * DMODEL);

        // 5) hid = relu(x @ W1 + b1)             (8192 x 2048, K=512)
        sgemm_tf32<<<dim3(DFF / 128, M / 128), 256, GEMM_SMEM_BYTES>>>(
            x, w1, b1b, hid, M, DFF, DMODEL, 1);

        // 6) attnb = hid @ W2 + b2               (8192 x 512, K=2048)
        sgemm_tf32<<<dim3(DMODEL / 128, M / 128), 256, GEMM_SMEM_BYTES>>>(
            hid, w2, b2b, attnb, M, DMODEL, DFF, 0);

        // 7) x = LN(x + ffn)
        add_ln_kernel<<<MROWS, 128>>>(x, attnb, g2 + layer * DMODEL, be2 + layer * DMODEL);
    }

    split_out_kernel<<<total4 / 256, 256>>>(x, out);
}

// round 15
// speedup vs baseline: 1.8534x; 1.0010x over previous
#include <cuda_runtime.h>

// ---------------- problem constants ----------------
#define NLAYER 4
#define BSZ    4
#define SEQ    2048
#define PLEN   1024
#define DMODEL 512
#define DFF    2048
#define NH     8
#define DHEAD  64
#define MROWS  (BSZ * SEQ)      // 8192 token rows

// ---------------- scratch (device globals: no allocation allowed) ----------
__device__ float g_x   [(size_t)MROWS * DMODEL];       // 16 MB residual stream
__device__ float g_qkv [(size_t)MROWS * 3 * DMODEL];   // 48 MB qkv
__device__ float g_attn[(size_t)MROWS * DMODEL];       // 16 MB attn out / ffn2 out
__device__ float g_hid [(size_t)MROWS * DFF];          // 64 MB ffn hidden / proj tmp

// ============================================================================
// TF32 tensor-core SGEMM: C[M,N] = A[M,K] @ B[K,N] + bias[N], optional ReLU.
// 128x128x32 tile, 256 threads (8 warps, 2x4), warp tile 64x32 via m16n8k8.
// A smem [128][36] (lda=36 -> conflict-free frag LDS), B smem [32][136].
// Inputs rounded to tf32 with cvt.rna in the producer path.
// ============================================================================
#define GA_LDA 36
#define GB_LDB 136
#define GA_BUF (128 * GA_LDA)              // 4608 floats
#define GB_BUF (32 * GB_LDB)               // 4352 floats
#define GEMM_SMEM_BYTES ((2 * GA_BUF + 2 * GB_BUF) * 4)   // 71680 B

__device__ __forceinline__ float to_tf32(float x) {
    unsigned u;
    asm("cvt.rna.tf32.f32 %0, %1;" : "=r"(u) : "f"(x));
    return __uint_as_float(u);
}

__device__ __forceinline__ void mma_tf32(float& d0, float& d1, float& d2, float& d3,
                                         unsigned a0, unsigned a1, unsigned a2, unsigned a3,
                                         unsigned b0, unsigned b1)
{
    asm volatile("mma.sync.aligned.m16n8k8.row.col.f32.tf32.tf32.f32 "
                 "{%0,%1,%2,%3}, {%4,%5,%6,%7}, {%8,%9}, {%0,%1,%2,%3};"
                 : "+f"(d0), "+f"(d1), "+f"(d2), "+f"(d3)
                 : "r"(a0), "r"(a1), "r"(a2), "r"(a3), "r"(b0), "r"(b1));
}

__global__ __launch_bounds__(256)
void sgemm_tf32(const float* __restrict__ A, const float* __restrict__ Bm,
                const float* __restrict__ bias, float* __restrict__ C,
                int M, int N, int K, int relu)
{
    extern __shared__ float sm[];
    float* As = sm;                  // [2][128][GA_LDA]
    float* Bs = sm + 2 * GA_BUF;     // [2][32][GB_LDB]

    const int tid  = threadIdx.x;
    const int bm   = blockIdx.y * 128;
    const int bn   = blockIdx.x * 128;
    const int lane = tid & 31;
    const int wid  = tid >> 5;
    const int wm0  = (wid & 1) * 64;        // warp m offset (2 warps along m)
    const int wn0  = (wid >> 1) * 32;       // warp n offset (4 warps along n)
    const int g    = lane >> 2;             // groupID 0..7
    const int tig  = lane & 3;              // thread-in-group 0..3

    // producer indices (both coalesced LDG, conflict-free STS)
    const int ar  = tid >> 3;               // A row 0..31 (+32 per it)
    const int ac4 = (tid & 7) * 4;          // A k-offset 0..28
    const int bk  = tid >> 3;               // B k row 0..31
    const int bc0 = tid & 7;                // B n-chunk 0..7 (+8 per it)

    float acc[4][4][4];
#pragma unroll
    for (int mt = 0; mt < 4; mt++)
#pragma unroll
        for (int nt = 0; nt < 4; nt++)
#pragma unroll
            for (int r = 0; r < 4; r++) acc[mt][nt][r] = 0.f;

    float4 pa[4], pb[4];

    // ---- preload k0 = 0 ----
#pragma unroll
    for (int it = 0; it < 4; it++) {
        pa[it] = *(const float4*)(A  + (size_t)(bm + ar + it * 32) * K + ac4);
        pb[it] = *(const float4*)(Bm + (size_t)bk * N + bn + (bc0 + it * 8) * 4);
    }
#pragma unroll
    for (int it = 0; it < 4; it++) {
        float4 v = pa[it];
        float4 w; w.x = to_tf32(v.x); w.y = to_tf32(v.y); w.z = to_tf32(v.z); w.w = to_tf32(v.w);
        *(float4*)(As + (ar + it * 32) * GA_LDA + ac4) = w;
        v = pb[it];
        w.x = to_tf32(v.x); w.y = to_tf32(v.y); w.z = to_tf32(v.z); w.w = to_tf32(v.w);
        *(float4*)(Bs + bk * GB_LDB + (bc0 + it * 8) * 4) = w;
    }
    __syncthreads();

    int buf = 0;
    for (int k0 = 0; k0 < K; k0 += 32) {
        const int kn = k0 + 32;
        if (kn < K) {
#pragma unroll
            for (int it = 0; it < 4; it++) {
                pa[it] = *(const float4*)(A  + (size_t)(bm + ar + it * 32) * K + kn + ac4);
                pb[it] = *(const float4*)(Bm + (size_t)(kn + bk) * N + bn + (bc0 + it * 8) * 4);
            }
        }

        const float* Ab = As + buf * GA_BUF;
        const float* Bb = Bs + buf * GB_BUF;
#pragma unroll
        for (int ks = 0; ks < 4; ks++) {
            unsigned bfr[4][2];
#pragma unroll
            for (int nt = 0; nt < 4; nt++) {
                const float* bp = Bb + (ks * 8 + tig) * GB_LDB + wn0 + nt * 8 + g;
                bfr[nt][0] = __float_as_uint(bp[0]);
                bfr[nt][1] = __float_as_uint(bp[4 * GB_LDB]);
            }
#pragma unroll
            for (int mt = 0; mt < 4; mt++) {
                const float* ap = Ab + (wm0 + mt * 16 + g) * GA_LDA + ks * 8 + tig;
                unsigned a0 = __float_as_uint(ap[0]);
                unsigned a1 = __float_as_uint(ap[8 * GA_LDA]);
                unsigned a2 = __float_as_uint(ap[4]);
                unsigned a3 = __float_as_uint(ap[8 * GA_LDA + 4]);
#pragma unroll
                for (int nt = 0; nt < 4; nt++)
                    mma_tf32(acc[mt][nt][0], acc[mt][nt][1], acc[mt][nt][2], acc[mt][nt][3],
                             a0, a1, a2, a3, bfr[nt][0], bfr[nt][1]);
            }
        }

        if (kn < K) {
            const int nb = buf ^ 1;
            float* Ad = As + nb * GA_BUF;
            float* Bd = Bs + nb * GB_BUF;
#pragma unroll
            for (int it = 0; it < 4; it++) {
                float4 v = pa[it];
                float4 w; w.x = to_tf32(v.x); w.y = to_tf32(v.y); w.z = to_tf32(v.z); w.w = to_tf32(v.w);
                *(float4*)(Ad + (ar + it * 32) * GA_LDA + ac4) = w;
                v = pb[it];
                w.x = to_tf32(v.x); w.y = to_tf32(v.y); w.z = to_tf32(v.z); w.w = to_tf32(v.w);
                *(float4*)(Bd + bk * GB_LDB + (bc0 + it * 8) * 4) = w;
            }
            __syncthreads();
            buf = nb;
        }
    }

    // ---- epilogue: bias (+ReLU), float2 stores ----
#pragma unroll
    for (int mt = 0; mt < 4; mt++) {
        const int row = bm + wm0 + mt * 16 + g;
#pragma unroll
        for (int nt = 0; nt < 4; nt++) {
            const int col = bn + wn0 + nt * 8 + 2 * tig;
            const float b0v = bias[col], b1v = bias[col + 1];
            float v0 = acc[mt][nt][0] + b0v;
            float v1 = acc[mt][nt][1] + b1v;
            float v2 = acc[mt][nt][2] + b0v;
            float v3 = acc[mt][nt][3] + b1v;
            if (relu) {
                v0 = fmaxf(v0, 0.f); v1 = fmaxf(v1, 0.f);
                v2 = fmaxf(v2, 0.f); v3 = fmaxf(v3, 0.f);
            }
            float2 o0; o0.x = v0; o0.y = v1;
            float2 o1; o1.x = v2; o1.y = v3;
            *(float2*)(C + (size_t)row * N + col)       = o0;
            *(float2*)(C + (size_t)(row + 8) * N + col) = o1;
        }
    }
}

// ============================================================================
// Fused sparse attention (flash-style) — unchanged from passing kernel.
// ============================================================================
constexpr int ATTN_SMEM_BYTES = (64 * 64 + 64 * 68 + 64 * 64) * 4;  // 50176

__global__ __launch_bounds__(128)
void attn_kernel(const float* __restrict__ qkv, float* __restrict__ out)
{
    constexpr int L = SEQ, Pp = PLEN, D = DMODEL, DH = DHEAD;
    constexpr int QT = 64, KT = 64, KLD = 68;
    extern __shared__ float sm[];
    float* Qs  = sm;                 // [DH][QT]
    float* KPs = sm + DH * QT;       // [DH][KLD] (K^T), reused as P [KT][KLD]
    float* Vs  = KPs + DH * KLD;     // [KT][DH]

    const int tid = threadIdx.x;
    const int l0  = blockIdx.x * QT;
    const int b   = blockIdx.y >> 3;
    const int h   = blockIdx.y & 7;
    const int rg  = tid >> 3;        // 0..15
    const int cg  = tid & 7;         // 0..7

    const float* qbase = qkv + ((size_t)b * L) * (3 * D) + h * DH;
    const float* kbase = qbase + D;
    const float* vbase = qbase + 2 * D;

#pragma unroll
    for (int it = 0; it < 8; it++) {
        int idx = tid + it * 128;
        int r = idx >> 4;
        int c = (idx & 15) << 2;
        float4 q4 = *(const float4*)(qbase + (size_t)(l0 + r) * (3 * D) + c);
        Qs[(c + 0) * QT + r] = q4.x * 0.125f;
        Qs[(c + 1) * QT + r] = q4.y * 0.125f;
        Qs[(c + 2) * QT + r] = q4.z * 0.125f;
        Qs[(c + 3) * QT + r] = q4.w * 0.125f;
    }

    float mrow[4], lrow[4], acc[4][8];
#pragma unroll
    for (int i = 0; i < 4; i++) {
        mrow[i] = -1e30f; lrow[i] = 0.f;
#pragma unroll
        for (int j = 0; j < 8; j++) acc[i][j] = 0.f;
    }
    __syncthreads();

    for (int kc = 0; kc < Pp; kc += KT) {
#pragma unroll
        for (int it = 0; it < 8; it++) {
            int idx = tid + it * 128;
            int r = idx >> 4;
            int c = (idx & 15) << 2;
            float4 k4 = *(const float4*)(kbase + (size_t)(kc + r) * (3 * D) + c);
            KPs[(c + 0) * KLD + r] = k4.x;
            KPs[(c + 1) * KLD + r] = k4.y;
            KPs[(c + 2) * KLD + r] = k4.z;
            KPs[(c + 3) * KLD + r] = k4.w;
            float4 v4 = *(const float4*)(vbase + (size_t)(kc + r) * (3 * D) + c);
            *(float4*)(Vs + r * DH + c) = v4;
        }
        __syncthreads();

        float s[4][8];
#pragma unroll
        for (int i = 0; i < 4; i++)
#pragma unroll
            for (int j = 0; j < 8; j++) s[i][j] = 0.f;
#pragma unroll 8
        for (int kk = 0; kk < DH; kk++) {
            float a[4], bv[8];
            *(float4*)a        = *(const float4*)(Qs  + kk * QT  + rg * 4);
            *(float4*)bv       = *(const float4*)(KPs + kk * KLD + cg * 8);
            *(float4*)(bv + 4) = *(const float4*)(KPs + kk * KLD + cg * 8 + 4);
#pragma unroll
            for (int i = 0; i < 4; i++)
#pragma unroll
                for (int j = 0; j < 8; j++)
                    s[i][j] = fmaf(a[i], bv[j], s[i][j]);
        }
        __syncthreads();

#pragma unroll
        for (int i = 0; i < 4; i++) {
            float rmax = s[i][0];
#pragma unroll
            for (int j = 1; j < 8; j++) rmax = fmaxf(rmax, s[i][j]);
            rmax = fmaxf(rmax, __shfl_xor_sync(0xffffffffu, rmax, 1));
            rmax = fmaxf(rmax, __shfl_xor_sync(0xffffffffu, rmax, 2));
            rmax = fmaxf(rmax, __shfl_xor_sync(0xffffffffu, rmax, 4));
            float mnew = fmaxf(mrow[i], rmax);
            float corr = __expf(mrow[i] - mnew);
            mrow[i] = mnew;
            float p[8], rs = 0.f;
#pragma unroll
            for (int j = 0; j < 8; j++) { p[j] = __expf(s[i][j] - mnew); rs += p[j]; }
            rs += __shfl_xor_sync(0xffffffffu, rs, 1);
            rs += __shfl_xor_sync(0xffffffffu, rs, 2);
            rs += __shfl_xor_sync(0xffffffffu, rs, 4);
            lrow[i] = lrow[i] * corr + rs;
#pragma unroll
            for (int j = 0; j < 8; j++) {
                acc[i][j] *= corr;
                KPs[(cg * 8 + j) * KLD + rg * 4 + i] = p[j];
            }
        }
        __syncthreads();

#pragma unroll 8
        for (int kk = 0; kk < KT; kk++) {
            float a[4], bv[8];
            *(float4*)a        = *(const float4*)(KPs + kk * KLD + rg * 4);
            *(float4*)bv       = *(const float4*)(Vs  + kk * DH  + cg * 8);
            *(float4*)(bv + 4) = *(const float4*)(Vs  + kk * DH  + cg * 8 + 4);
#pragma unroll
            for (int i = 0; i < 4; i++)
#pragma unroll
                for (int j = 0; j < 8; j++)
                    acc[i][j] = fmaf(a[i], bv[j], acc[i][j]);
        }
        __syncthreads();
    }

    const bool isgen = (l0 >= Pp);
#pragma unroll
    for (int i = 0; i < 4; i++) {
        const int r  = rg * 4 + i;
        const int lq = l0 + r;
        if (isgen) {
            const float* ks = kbase + (size_t)lq * (3 * D);
            float part = 0.f;
#pragma unroll
            for (int kk2 = 0; kk2 < 8; kk2++) {
                int k = cg * 8 + kk2;
                part += Qs[k * QT + r] * ks[k];
            }
            part += __shfl_xor_sync(0xffffffffu, part, 1);
            part += __shfl_xor_sync(0xffffffffu, part, 2);
            part += __shfl_xor_sync(0xffffffffu, part, 4);
            const float dlog = part;
            float mnew = fmaxf(mrow[i], dlog);
            float corr = __expf(mrow[i] - mnew);
            float ed   = __expf(dlog - mnew);
            lrow[i] = lrow[i] * corr + ed;
            const float* vs = vbase + (size_t)lq * (3 * D) + cg * 8;
            float4 v0 = *(const float4*)(vs);
            float4 v1 = *(const float4*)(vs + 4);
            float vv[8] = {v0.x, v0.y, v0.z, v0.w, v1.x, v1.y, v1.z, v1.w};
#pragma unroll
            for (int j = 0; j < 8; j++)
                acc[i][j] = acc[i][j] * corr + ed * vv[j];
        }
        const float inv = 1.f / lrow[i];
        float* op = out + ((size_t)b * L + lq) * D + h * DH + cg * 8;
        float4 o0, o1;
        o0.x = acc[i][0] * inv; o0.y = acc[i][1] * inv;
        o0.z = acc[i][2] * inv; o0.w = acc[i][3] * inv;
        o1.x = acc[i][4] * inv; o1.y = acc[i][5] * inv;
        o1.z = acc[i][6] * inv; o1.w = acc[i][7] * inv;
        *(float4*)op       = o0;
        *(float4*)(op + 4) = o1;
    }
}

// ============================================================================
// Fused residual add + LayerNorm (in-place on x): x = LN(x + delta)*g + b
// ============================================================================
__global__ __launch_bounds__(128)
void add_ln_kernel(float* __restrict__ x, const float* __restrict__ delta,
                   const float* __restrict__ gamma, const float* __restrict__ beta)
{
    __shared__ float rs[4], rq[4];
    const int tid = threadIdx.x;
    const size_t off = (size_t)blockIdx.x * DMODEL + tid * 4;
    float4 a  = *(const float4*)(x + off);
    float4 d4 = *(const float4*)(delta + off);
    float v0 = a.x + d4.x, v1 = a.y + d4.y, v2 = a.z + d4.z, v3 = a.w + d4.w;
    float s = v0 + v1 + v2 + v3;
    float q = v0 * v0 + v1 * v1 + v2 * v2 + v3 * v3;
#pragma unroll
    for (int o = 16; o > 0; o >>= 1) {
        s += __shfl_xor_sync(0xffffffffu, s, o);
        q += __shfl_xor_sync(0xffffffffu, q, o);
    }
    if ((tid & 31) == 0) { rs[tid >> 5] = s; rq[tid >> 5] = q; }
    __syncthreads();
    const float ts = rs[0] + rs[1] + rs[2] + rs[3];
    const float tq = rq[0] + rq[1] + rq[2] + rq[3];
    const float mu   = ts * (1.0f / DMODEL);
    const float var  = tq * (1.0f / DMODEL) - mu * mu;
    const float rstd = rsqrtf(var + 1e-5f);
    float4 g4 = *(const float4*)(gamma + tid * 4);
    float4 b4 = *(const float4*)(beta + tid * 4);
    float4 o;
    o.x = (v0 - mu) * rstd * g4.x + b4.x;
    o.y = (v1 - mu) * rstd * g4.y + b4.y;
    o.z = (v2 - mu) * rstd * g4.z + b4.z;
    o.w = (v3 - mu) * rstd * g4.w + b4.w;
    *(float4*)(x + off) = o;
}

// ============================================================================
// Concat pcpt/gen into x; split x into (pcpt_out, gen_out) at the end.
// ============================================================================
__global__ void concat_in_kernel(const float* __restrict__ pcpt,
                                 const float* __restrict__ gen,
                                 float* __restrict__ x)
{
    const size_t i = (size_t)blockIdx.x * blockDim.x + threadIdx.x;
    const size_t row = i >> 7;
    const int    c4  = (int)(i & 127);
    const size_t b   = row >> 11;
    const int    l   = (int)(row & 2047);
    const float4* src;
    if (l < PLEN) src = (const float4*)pcpt + ((b * PLEN + l) * 128 + c4);
    else          src = (const float4*)gen  + ((b * PLEN + (l - PLEN)) * 128 + c4);
    ((float4*)x)[i] = *src;
}

__global__ void split_out_kernel(const float* __restrict__ x, float* __restrict__ out)
{
    const size_t i = (size_t)blockIdx.x * blockDim.x + threadIdx.x;
    const size_t row = i >> 7;
    const int    c4  = (int)(i & 127);
    const size_t b   = row >> 11;
    const int    l   = (int)(row & 2047);
    size_t dst;
    if (l < PLEN) dst = (b * PLEN + l) * 128 + c4;
    else          dst = (size_t)BSZ * PLEN * 128 + (b * PLEN + (l - PLEN)) * 128 + c4;
    ((float4*)out)[dst] = ((const float4*)x)[i];
}

// ============================================================================
// kernel_launch
// ============================================================================
extern "C" void kernel_launch(void* const* d_in, const int* in_sizes, int n_in,
                              void* d_out, int out_size)
{
    (void)in_sizes; (void)n_in; (void)out_size;
    const float* pcpt = (const float*)d_in[0];
    const float* gen  = (const float*)d_in[1];
    const float* Wqkv = (const float*)d_in[3];
    const float* bqkv = (const float*)d_in[4];
    const float* Wo   = (const float*)d_in[5];
    const float* bo   = (const float*)d_in[6];
    const float* W1   = (const float*)d_in[7];
    const float* b1   = (const float*)d_in[8];
    const float* W2   = (const float*)d_in[9];
    const float* b2   = (const float*)d_in[10];
    const float* g1   = (const float*)d_in[11];
    const float* be1  = (const float*)d_in[12];
    const float* g2   = (const float*)d_in[13];
    const float* be2  = (const float*)d_in[14];
    float* out = (float*)d_out;

    float *x, *qkvb, *attnb, *hid;
    cudaGetSymbolAddress((void**)&x,     g_x);
    cudaGetSymbolAddress((void**)&qkvb,  g_qkv);
    cudaGetSymbolAddress((void**)&attnb, g_attn);
    cudaGetSymbolAddress((void**)&hid,   g_hid);

    cudaFuncSetAttribute((const void*)attn_kernel,
                         cudaFuncAttributeMaxDynamicSharedMemorySize,
                         ATTN_SMEM_BYTES);
    cudaFuncSetAttribute((const void*)sgemm_tf32,
                         cudaFuncAttributeMaxDynamicSharedMemorySize,
                         GEMM_SMEM_BYTES);

    const int total4 = MROWS * DMODEL / 4;
    concat_in_kernel<<<total4 / 256, 256>>>(pcpt, gen, x);

    constexpr int M = MROWS;
    for (int layer = 0; layer < NLAYER; layer++) {
        const float* wq  = Wqkv + (size_t)layer * DMODEL * 3 * DMODEL;
        const float* bq  = bqkv + (size_t)layer * 3 * DMODEL;
        const float* wo  = Wo   + (size_t)layer * DMODEL * DMODEL;
        const float* bob = bo   + (size_t)layer * DMODEL;
        const float* w1  = W1   + (size_t)layer * DMODEL * DFF;
        const float* b1b = b1   + (size_t)layer * DFF;
        const float* w2  = W2   + (size_t)layer * DFF * DMODEL;
        const float* b2b = b2   + (size_t)layer * DMODEL;

        // 1) qkv = x @ Wqkv + bqkv               (8192 x 1536, K=512)
        sgemm_tf32<<<dim3(3 * DMODEL / 128, M / 128), 256, GEMM_SMEM_BYTES>>>(
            x, wq, bq, qkvb, M, 3 * DMODEL, DMODEL, 0);

        // 2) fused sparse attention -> attnb
        attn_kernel<<<dim3(SEQ / 64, BSZ * NH), 128, ATTN_SMEM_BYTES>>>(qkvb, attnb);

        // 3) proj = attn @ Wo + bo -> hid (tmp)  (8192 x 512, K=512)
        sgemm_tf32<<<dim3(DMODEL / 128, M / 128), 256, GEMM_SMEM_BYTES>>>(
            attnb, wo, bob, hid, M, DMODEL, DMODEL, 0);

        // 4) x = LN(x + proj)
        add_ln_kernel<<<MROWS, 128>>>(x, hid, g1 + layer * DMODEL, be1 + layer * DMODEL);

        // 5) hid = relu(x @ W1 + b1)             (8192 x 2048, K=512)
        sgemm_tf32<<<dim3(DFF / 128, M / 128), 256, GEMM_SMEM_BYTES>>>(
            x, w1, b1b, hid, M, DFF, DMODEL, 1);

        // 6) attnb = hid @ W2 + b2               (8192 x 512, K=2048)
        sgemm_tf32<<<dim3(DMODEL / 128, M / 128), 256, GEMM_SMEM_BYTES>>>(
            hid, w2, b2b, attnb, M, DMODEL, DFF, 0);

        // 7) x = LN(x + ffn)
        add_ln_kernel<<<MROWS, 128>>>(x, attnb, g2 + layer * DMODEL, be2 + layer * DMODEL);
    }

    split_out_kernel<<<total4 / 256, 256>>>(x, out);
}